// round 7
// baseline (speedup 1.0000x reference)
#include <cuda_runtime.h>
#include <stdint.h>

// Problem constants (fixed shapes per reference)
#define VOCAB   20000
#define TOPK    8
#define GLOVE   300
#define ROW_F   (TOPK * 2 * GLOVE)   // 4800 floats per vocab row
#define OUTC    100
#define B       32
#define L       128
#define NLAB    8
#define NPOS    (B * L)              // 4096
#define NLABTOT (NPOS * NLAB)        // 32768

#define NSM     148
#define NSTAGE  3                    // cp.async row-buffer depth
#define RBATCH  4                    // rows per projection batch
#define WPITCH  101                  // W smem pitch (stride 101 mod 32 = 5 -> conflict-free)
#define SPITCH  304                  // s smem pitch (16B-aligned slots)

// Device scratch (no allocations allowed)
__device__ unsigned int g_flags[VOCAB];
__device__ float g_P[VOCAB * OUTC];       // 8 MB: per-vocab projected (prescaled /128) 100-vec

// cp.async helpers (raw PTX; 16B, L1-bypass streaming)
#define CP_ASYNC16(dst_sm_u32, src_gen) \
    asm volatile("cp.async.cg.shared.global [%0], [%1], 16;" \
                 :: "r"(dst_sm_u32), "l"(src_gen) : "memory")
#define CP_COMMIT() asm volatile("cp.async.commit_group;" ::: "memory")
#define CP_WAIT_PRIOR2() asm volatile("cp.async.wait_group %0;" :: "n"(NSTAGE - 1) : "memory")

// ---------------------------------------------------------------------------
// Kernel 1: clear usage flags
// ---------------------------------------------------------------------------
__global__ void k_clear_flags() {
    int i = blockIdx.x * blockDim.x + threadIdx.x;
    if (i < VOCAB) g_flags[i] = 0u;
}

// ---------------------------------------------------------------------------
// Kernel 2: mark used vocab entries
// ---------------------------------------------------------------------------
__global__ void k_mark_flags(const int* __restrict__ labels) {
    int i = blockIdx.x * blockDim.x + threadIdx.x;
    if (i < NLABTOT) g_flags[labels[i]] = 1u;
}

// ---------------------------------------------------------------------------
// Kernel 3: persistent fused stream + reduce + project.
// Grid = 148 (1 CTA/SM). Each block:
//   - builds its list of flagged vocab rows (stride-148 assignment)
//   - stages W^T [300][101] in smem once          (121 KB; W reuse across all rows)
//   - cp.async pipeline (depth 3) streams 19.2KB rows at the DRAM floor
//   - reduces each row's 16 subrows -> s slot (x4 slots)
//   - every 4 rows: projection P = s . W^T batched over 4 rows
//     (each W element LDS'd once per 4 rows -> smem traffic under stream time)
// ---------------------------------------------------------------------------
#define ROWBUF_F  ROW_F                       // 4800 floats per stage
#define DYN_W     (GLOVE * WPITCH)            // 30300
#define DYN_RB    (NSTAGE * ROWBUF_F)         // 14400
#define DYN_S     (RBATCH * SPITCH)           // 1216
#define DYN_PS    (2 * RBATCH * OUTC)         // 800
#define DYN_FLOATS (DYN_W + DYN_RB + DYN_S + DYN_PS)
#define DYN_BYTES  (DYN_FLOATS * 4)           // 186,864 B

__global__ __launch_bounds__(256, 1) void k_fused(
    const float* __restrict__ table,
    const float* __restrict__ w)              // [100, 300]
{
    extern __shared__ float dyn[];
    float* W_sh  = dyn;                       // [300][101]  (k-major, out minor)
    float* rbuf  = dyn + DYN_W;               // [3][4800]
    float* s_sh  = rbuf + DYN_RB;             // [4][304]
    float* psum  = s_sh + DYN_S;              // [2][4][100]

    __shared__ int s_list[144];
    __shared__ int s_cnt;

    const int t = threadIdx.x;
    const int b = blockIdx.x;

    // ---- build flagged-row list (strided assignment; order irrelevant) ----
    if (t == 0) s_cnt = 0;
    __syncthreads();
    {
        const int v = b + NSM * t;
        if (v < VOCAB && t < 144) {
            if (g_flags[v]) {
                int p = atomicAdd(&s_cnt, 1);
                s_list[p] = v;
            }
        }
    }

    // ---- stage W transposed: W_sh[k*101+o] = w[o*300+k] ----
    // coalesced LDG (j consecutive -> k consecutive), STS stride 101 conflict-free
    for (int j = t; j < OUTC * GLOVE; j += 256) {
        const int o = j / GLOVE;
        const int k = j % GLOVE;
        W_sh[k * WPITCH + o] = w[j];
    }
    __syncthreads();

    const int nrows = s_cnt;

    // smem u32 bases for cp.async
    const unsigned rbuf_sm = (unsigned)__cvta_generic_to_shared(rbuf);

    // ---- prologue: issue NSTAGE groups (empty-commit beyond nrows) ----
    for (int s2 = 0; s2 < NSTAGE; ++s2) {
        if (s2 < nrows) {
            const float* src = table + (size_t)s_list[s2] * ROW_F;
            const unsigned dst = rbuf_sm + (unsigned)(s2 * ROWBUF_F) * 4u;
            for (int c = t; c < ROW_F / 4; c += 256)
                CP_ASYNC16(dst + (unsigned)c * 16u, src + c * 4);
        }
        CP_COMMIT();
    }

    const float scale = 1.0f / 128.0f;

    for (int i = 0; i < nrows; ++i) {
        CP_WAIT_PRIOR2();          // this thread's chunks of row i landed
        __syncthreads();           // all threads' chunks visible; s slot free

        // ---- reduce row i: 16 subrows -> s_sh[i&3] ----
        const float* rb = rbuf + (i % NSTAGE) * ROWBUF_F;
        float* sd = s_sh + (i & 3) * SPITCH;
        {
            float s = 0.0f;
            #pragma unroll
            for (int r = 0; r < 16; ++r) s += rb[r * GLOVE + t];
            sd[t] = s * scale;
        }
        if (t < GLOVE - 256) {
            const int d = t + 256;
            float s = 0.0f;
            #pragma unroll
            for (int r = 0; r < 16; ++r) s += rb[r * GLOVE + d];
            sd[d] = s * scale;
        }
        __syncthreads();           // reduce done: rbuf slot reusable, s slot ready

        // ---- issue cp.async for row i+NSTAGE into the freed slot ----
        {
            const int nx = i + NSTAGE;
            if (nx < nrows) {
                const float* src = table + (size_t)s_list[nx] * ROW_F;
                const unsigned dst = rbuf_sm + (unsigned)((nx % NSTAGE) * ROWBUF_F) * 4u;
                for (int c = t; c < ROW_F / 4; c += 256)
                    CP_ASYNC16(dst + (unsigned)c * 16u, src + c * 4);
            }
            CP_COMMIT();
        }

        // ---- projection every RBATCH rows (and at the tail) ----
        const int inb = i & 3;
        const bool flush = (inb == RBATCH - 1) || (i == nrows - 1);
        if (flush) {
            const int cnt  = inb + 1;       // valid rows in this batch
            const int base = i - inb;       // first row index of batch
            // 200 active threads: warps 0-3 -> k-half 0 (t<100),
            // warps 4-7 -> k-half 1 (128<=t<228). No mixed-h warps.
            int o = -1, h = 0;
            if (t < OUTC)                   { o = t;       h = 0; }
            else if (t >= 128 && t < 228)   { o = t - 128; h = 1; }
            if (o >= 0) {
                const int k0 = h ? 152 : 0;
                const int kn = h ? 148 : 152;   // both %4 == 0, float4-aligned
                float acc[RBATCH] = {0.f, 0.f, 0.f, 0.f};
                for (int j = 0; j < kn; j += 4) {
                    const int k = k0 + j;
                    const float w0 = W_sh[(k + 0) * WPITCH + o];
                    const float w1 = W_sh[(k + 1) * WPITCH + o];
                    const float w2 = W_sh[(k + 2) * WPITCH + o];
                    const float w3 = W_sh[(k + 3) * WPITCH + o];
                    #pragma unroll
                    for (int r = 0; r < RBATCH; ++r) {
                        const float4 sv =
                            *reinterpret_cast<const float4*>(s_sh + r * SPITCH + k);
                        acc[r] = fmaf(sv.x, w0, acc[r]);
                        acc[r] = fmaf(sv.y, w1, acc[r]);
                        acc[r] = fmaf(sv.z, w2, acc[r]);
                        acc[r] = fmaf(sv.w, w3, acc[r]);
                    }
                }
                #pragma unroll
                for (int r = 0; r < RBATCH; ++r)
                    psum[h * (RBATCH * OUTC) + r * OUTC + o] = acc[r];
            }
            __syncthreads();       // psum ready
            // combine halves + store P rows
            for (int j = t; j < cnt * OUTC; j += 256) {
                const int r = j / OUTC;
                const int o2 = j % OUTC;
                g_P[(size_t)s_list[base + r] * OUTC + o2] =
                    psum[r * OUTC + o2] + psum[RBATCH * OUTC + r * OUTC + o2];
            }
            // next iteration's first __syncthreads orders this vs s_sh reuse
        }
    }
}

// ---------------------------------------------------------------------------
// Kernel 4: output gather.  out[pos][o] = sum_8 P[label][o] + bias[o].
// ---------------------------------------------------------------------------
#define OUT_THREADS 256
#define OUT_TOTAL   (NPOS * 25)

__global__ __launch_bounds__(OUT_THREADS) void k_out(
    const int* __restrict__ labels,
    const float* __restrict__ bias,
    float* __restrict__ out)
{
    const int i = blockIdx.x * OUT_THREADS + threadIdx.x;
    if (i >= OUT_TOTAL) return;
    const int p = i / 25;
    const int q = (i % 25) * 4;

    const int* __restrict__ lab = labels + p * NLAB;
    int l[NLAB];
    #pragma unroll
    for (int j = 0; j < NLAB; ++j) l[j] = lab[j];

    float4 s = *reinterpret_cast<const float4*>(&bias[q]);
    #pragma unroll
    for (int j = 0; j < NLAB; ++j) {
        const float4 v = *reinterpret_cast<const float4*>(&g_P[(size_t)l[j] * OUTC + q]);
        s.x += v.x; s.y += v.y; s.z += v.z; s.w += v.w;
    }
    *reinterpret_cast<float4*>(&out[p * OUTC + q]) = s;
}

// ---------------------------------------------------------------------------
extern "C" void kernel_launch(void* const* d_in, const int* in_sizes, int n_in,
                              void* d_out, int out_size) {
    const int*   labels = (const int*)  d_in[0];   // [32, 128, 8] int32
    const float* table  = (const float*)d_in[1];   // [20000, 8, 600] f32
    const float* conv_w = (const float*)d_in[2];   // [100, 300]
    const float* conv_b = (const float*)d_in[3];   // [100]
    float*       out    = (float*)d_out;           // [32, 128, 100]

    (void)in_sizes; (void)n_in; (void)out_size;

    cudaFuncSetAttribute(k_fused, cudaFuncAttributeMaxDynamicSharedMemorySize,
                         DYN_BYTES);

    k_clear_flags<<<(VOCAB + 255) / 256, 256>>>();
    k_mark_flags<<<(NLABTOT + 255) / 256, 256>>>(labels);
    k_fused<<<NSM, 256, DYN_BYTES>>>(table, conv_w);
    k_out<<<(OUT_TOTAL + OUT_THREADS - 1) / OUT_THREADS, OUT_THREADS>>>(labels, conv_b, out);
}

// round 8
// speedup vs baseline: 2.4501x; 2.4501x over previous
#include <cuda_runtime.h>
#include <stdint.h>

// Problem constants (fixed shapes per reference)
#define VOCAB   20000
#define TOPK    8
#define GLOVE   300
#define ROW_F   (TOPK * 2 * GLOVE)   // 4800 floats per vocab row
#define OUTC    100
#define B       32
#define L       128
#define NLAB    8
#define NPOS    (B * L)              // 4096
#define NLABTOT (NPOS * NLAB)        // 32768

// Device scratch (no allocations allowed)
__device__ unsigned int g_flags[VOCAB];
__device__ float g_lsum[VOCAB * GLOVE];        // 24 MB: per-vocab summed+prescaled 300-vec
__device__ float g_part[4 * NPOS * OUTC];      // 6.5 MB: split-K partials

// ---------------------------------------------------------------------------
// Kernel 1: clear usage flags
// ---------------------------------------------------------------------------
__global__ void k_clear_flags() {
    int i = blockIdx.x * blockDim.x + threadIdx.x;
    if (i < VOCAB) g_flags[i] = 0u;
}

// ---------------------------------------------------------------------------
// Kernel 2: mark used vocab entries
// ---------------------------------------------------------------------------
__global__ void k_mark_flags(const int* __restrict__ labels) {
    int i = blockIdx.x * blockDim.x + threadIdx.x;
    if (i < NLABTOT) g_flags[labels[i]] = 1u;
}

// ---------------------------------------------------------------------------
// Kernel 3: per-vocab row reduction (DRAM floor, ~310 MB @ ~6 TB/s).
// Proven ~52 us. Do not touch.
// ---------------------------------------------------------------------------
__global__ __launch_bounds__(256) void k_rowsum(const float* __restrict__ table) {
    const int v = blockIdx.x;
    if (!g_flags[v]) return;
    const float* __restrict__ row = table + (size_t)v * ROW_F;
    const int t = threadIdx.x;
    const float scale = 1.0f / 128.0f;

    {
        float s = 0.0f;
        #pragma unroll
        for (int r = 0; r < 16; ++r) s += row[r * GLOVE + t];
        g_lsum[v * GLOVE + t] = s * scale;
    }
    if (t < GLOVE - 256) {
        const int d = t + 256;
        float s = 0.0f;
        #pragma unroll
        for (int r = 0; r < 16; ++r) s += row[r * GLOVE + d];
        g_lsum[v * GLOVE + d] = s * scale;
    }
}

// ---------------------------------------------------------------------------
// Kernel 4: split-K GEMM with fused averaging gather.
//   part[kc][p][o] = sum_{k in chunk kc} A[p][k] * W[o][k]
//   where A[p][k] = sum_8 g_lsum[label][k]  (gathered in-block from L2)
// Grid 512 = 128 pos-tiles(32) x 4 K-chunks(75). 200 threads/block.
// Thread tile 4 pos x 4 outs: per k one float4 A + one float4 W -> 16 FMA.
// smem: A_t [75][36] ([k][pos], pitch mult-of-4 for aligned LDS.128),
//       W_t [75][104] ([k][out]).  ~43 KB -> 3-4 blocks/SM, ~22 warps/SM.
// ---------------------------------------------------------------------------
#define KSPLIT  4
#define KCH     75
#define PTILE   32
#define NPT     (NPOS / PTILE)     // 128
#define GT6     200
#define AP      36
#define WP      104

__global__ __launch_bounds__(GT6) void k_gemm6(
    const int* __restrict__ labels,
    const float* __restrict__ w)          // [100, 300]
{
    __shared__ float A_t[KCH][AP];        // [k][pos]
    __shared__ float W_t[KCH][WP];        // [k][out]
    __shared__ int   s_lab[PTILE * NLAB];

    const int tid   = threadIdx.x;
    const int kc    = blockIdx.x & (KSPLIT - 1);
    const int pt    = blockIdx.x >> 2;
    const int pbase = pt * PTILE;
    const int k0    = kc * KCH;

    // stage labels
    for (int i = tid; i < PTILE * NLAB; i += GT6)
        s_lab[i] = labels[pbase * NLAB + i];

    // stage W chunk transposed: W_t[kk][o] = w[o*300 + k0+kk]
    for (int j = tid; j < OUTC * KCH; j += GT6) {
        const int o  = j / KCH;
        const int kk = j % KCH;
        W_t[kk][o] = w[o * GLOVE + k0 + kk];
    }
    __syncthreads();   // labels visible for gather

    // fused gather: A_t[kk][pp] = sum_8 g_lsum[lab][k0+kk]
    for (int j = tid; j < PTILE * KCH; j += GT6) {
        const int pp = j / KCH;
        const int kk = j % KCH;
        const int* lab = &s_lab[pp * NLAB];
        float s = 0.0f;
        #pragma unroll
        for (int m = 0; m < NLAB; ++m)
            s += g_lsum[lab[m] * GLOVE + k0 + kk];
        A_t[kk][pp] = s;
    }
    __syncthreads();

    const int pg = tid / 25;   // 0..7 -> pos quad
    const int og = tid % 25;   // 0..24 -> out quad

    float acc[4][4];
    #pragma unroll
    for (int i = 0; i < 4; ++i)
        #pragma unroll
        for (int j = 0; j < 4; ++j) acc[i][j] = 0.0f;

    #pragma unroll 3
    for (int kk = 0; kk < KCH; ++kk) {
        const float4 a  = *reinterpret_cast<const float4*>(&A_t[kk][pg * 4]);
        const float4 wv = *reinterpret_cast<const float4*>(&W_t[kk][og * 4]);
        const float av[4] = {a.x, a.y, a.z, a.w};
        const float wa[4] = {wv.x, wv.y, wv.z, wv.w};
        #pragma unroll
        for (int i = 0; i < 4; ++i)
            #pragma unroll
            for (int j = 0; j < 4; ++j)
                acc[i][j] = fmaf(av[i], wa[j], acc[i][j]);
    }

    // write partials: g_part[kc][pos][out], float4 per pos
    float* dst = g_part + (size_t)kc * (NPOS * OUTC);
    #pragma unroll
    for (int i = 0; i < 4; ++i) {
        const int p = pbase + pg * 4 + i;
        float4 r = make_float4(acc[i][0], acc[i][1], acc[i][2], acc[i][3]);
        *reinterpret_cast<float4*>(&dst[p * OUTC + og * 4]) = r;
    }
}

// ---------------------------------------------------------------------------
// Kernel 5: final reduction of split-K partials + bias.
// ---------------------------------------------------------------------------
#define FIN_THREADS 256
#define FIN_TOTAL   (NPOS * 25)

__global__ __launch_bounds__(FIN_THREADS) void k_final(
    const float* __restrict__ bias,
    float* __restrict__ out)
{
    const int i = blockIdx.x * FIN_THREADS + threadIdx.x;
    if (i >= FIN_TOTAL) return;
    const int p = i / 25;
    const int q = (i % 25) * 4;

    float4 s = *reinterpret_cast<const float4*>(&bias[q]);
    #pragma unroll
    for (int kc = 0; kc < KSPLIT; ++kc) {
        const float4 v = *reinterpret_cast<const float4*>(
            &g_part[(size_t)kc * (NPOS * OUTC) + p * OUTC + q]);
        s.x += v.x; s.y += v.y; s.z += v.z; s.w += v.w;
    }
    *reinterpret_cast<float4*>(&out[p * OUTC + q]) = s;
}

// ---------------------------------------------------------------------------
extern "C" void kernel_launch(void* const* d_in, const int* in_sizes, int n_in,
                              void* d_out, int out_size) {
    const int*   labels = (const int*)  d_in[0];   // [32, 128, 8] int32
    const float* table  = (const float*)d_in[1];   // [20000, 8, 600] f32
    const float* conv_w = (const float*)d_in[2];   // [100, 300]
    const float* conv_b = (const float*)d_in[3];   // [100]
    float*       out    = (float*)d_out;           // [32, 128, 100]

    (void)in_sizes; (void)n_in; (void)out_size;

    k_clear_flags<<<(VOCAB + 255) / 256, 256>>>();
    k_mark_flags<<<(NLABTOT + 255) / 256, 256>>>(labels);
    k_rowsum<<<VOCAB, 256>>>(table);
    k_gemm6<<<NPT * KSPLIT, GT6>>>(labels, conv_w);
    k_final<<<(FIN_TOTAL + FIN_THREADS - 1) / FIN_THREADS, FIN_THREADS>>>(conv_b, out);
}